// round 1
// baseline (speedup 1.0000x reference)
#include <cuda_runtime.h>
#include <math.h>

#define B_ 512
#define N_ 127
#define D_ 300
#define FD 1200   // 4*D : [i | o | u | f]

// ---- scratch (static device allocations; no runtime alloc allowed) ----
__device__ float g_Z[(size_t)N_ * B_ * FD];   // x @ [Wioux|Wfx] + bias   (312 MB)
__device__ float g_P[(size_t)N_ * B_ * FD];   // h @ [Wiouh|Wfh]          (312 MB)
__device__ float g_C[(size_t)N_ * B_ * D_];   // cell states              (78 MB)
__device__ float g_Wc[D_ * FD];               // [Wioux | Wfx]
__device__ float g_W2[D_ * FD];               // [Wiouh | Wfh]
__device__ float g_bc[FD];                    // combined bias for Z

__device__ __forceinline__ float sigm(float x) { return 1.0f / (1.0f + __expf(-x)); }

// ---- pack weights + combined bias ----
__global__ void pack_k(const float* __restrict__ Wioux, const float* __restrict__ bioux,
                       const float* __restrict__ Wiouh, const float* __restrict__ biouh,
                       const float* __restrict__ Wfx,  const float* __restrict__ bfx,
                       const float* __restrict__ Wfh,  const float* __restrict__ bfh) {
    int idx = blockIdx.x * blockDim.x + threadIdx.x;
    if (idx >= D_ * FD) return;
    int k = idx / FD, col = idx % FD;
    float wc, w2;
    if (col < 3 * D_) { wc = Wioux[k * 3 * D_ + col]; w2 = Wiouh[k * 3 * D_ + col]; }
    else              { wc = Wfx[k * D_ + col - 3 * D_]; w2 = Wfh[k * D_ + col - 3 * D_]; }
    g_Wc[idx] = wc;
    g_W2[idx] = w2;
    if (idx < FD)
        g_bc[idx] = (idx < 3 * D_) ? (bioux[idx] + biouh[idx])
                                   : (bfx[idx - 3 * D_] + bfh[idx - 3 * D_]);
}

// ---- GEMM: Out[R, 0..1200) = A_row(R) . W  (+ bias) ----
// Row R -> node j = node_start + R/512, batch b = R%512.
// A rows are read from a (B, N, D) b-major tensor: Abase + (b*N_ + j)*D_.
// Out rows are contiguous: Out + R*FD.  M is always a multiple of 128.
#define BM 128
#define BN 128
#define BK 8

__global__ __launch_bounds__(256) void gemm_k(
    const float* __restrict__ Abase, int node_start,
    const float* __restrict__ W, const float* __restrict__ bias,
    float* __restrict__ Out)
{
    __shared__ float As[BK][BM];
    __shared__ float Bs[BK][BN];

    const int t = threadIdx.x;
    const int row0 = blockIdx.x * BM;
    const int col0 = blockIdx.y * BN;

    // A-tile loader mapping: each thread loads one float4 (half a k-row)
    const int r_loc = t >> 1;          // 0..127
    const int q     = t & 1;           // which float4 of the 8-wide k strip
    const int R     = row0 + r_loc;
    const int jn    = node_start + (R >> 9);
    const int bb    = R & (B_ - 1);
    const float* arow = Abase + ((size_t)bb * N_ + jn) * D_;

    // B-tile loader mapping
    const int kk_b = t >> 5;           // 0..7
    const int c4   = (t & 31) * 4;     // 0,4,...,124
    const int colB = col0 + c4;

    const int tx = t & 15, ty = t >> 4;

    float acc[8][8];
#pragma unroll
    for (int i = 0; i < 8; i++)
#pragma unroll
        for (int j2 = 0; j2 < 8; j2++) acc[i][j2] = 0.0f;

    for (int kt = 0; kt < D_; kt += BK) {
        // load A tile
        int k0 = kt + q * 4;
        float4 va;
        if (k0 + 3 < D_) {
            va = *(const float4*)(arow + k0);
        } else {
            va.x = (k0     < D_) ? arow[k0]     : 0.0f;
            va.y = (k0 + 1 < D_) ? arow[k0 + 1] : 0.0f;
            va.z = (k0 + 2 < D_) ? arow[k0 + 2] : 0.0f;
            va.w = 0.0f;
        }
        As[q * 4 + 0][r_loc] = va.x;
        As[q * 4 + 1][r_loc] = va.y;
        As[q * 4 + 2][r_loc] = va.z;
        As[q * 4 + 3][r_loc] = va.w;

        // load B tile (weights, row-major 300 x 1200)
        int kr = kt + kk_b;
        float4 vb = make_float4(0.f, 0.f, 0.f, 0.f);
        if (kr < D_ && colB < FD)
            vb = *(const float4*)(W + (size_t)kr * FD + colB);
        Bs[kk_b][c4 + 0] = vb.x;
        Bs[kk_b][c4 + 1] = vb.y;
        Bs[kk_b][c4 + 2] = vb.z;
        Bs[kk_b][c4 + 3] = vb.w;

        __syncthreads();

#pragma unroll
        for (int kk = 0; kk < BK; ++kk) {
            float a[8], bv[8];
#pragma unroll
            for (int i = 0; i < 8; i++) a[i] = As[kk][ty * 8 + i];
#pragma unroll
            for (int i = 0; i < 8; i++) bv[i] = Bs[kk][tx * 8 + i];
#pragma unroll
            for (int i = 0; i < 8; i++)
#pragma unroll
                for (int j2 = 0; j2 < 8; j2++)
                    acc[i][j2] += a[i] * bv[j2];
        }
        __syncthreads();
    }

#pragma unroll
    for (int i = 0; i < 8; i++) {
        int Rr = row0 + ty * 8 + i;
        size_t obase = (size_t)Rr * FD;
#pragma unroll
        for (int j2 = 0; j2 < 8; j2++) {
            int cc = col0 + tx * 8 + j2;
            if (cc < FD) {
                float v = acc[i][j2];
                if (bias) v += bias[cc];
                Out[obase + cc] = v;
            }
        }
    }
}

// ---- leaves (nodes 63..126): c = sig(z_i)*tanh(z_u); h = sig(z_o)*tanh(c) ----
__global__ void leaf_k(float* __restrict__ out) {
    int idx = blockIdx.x * blockDim.x + threadIdx.x;
    const int total = 64 * B_ * D_;
    if (idx >= total) return;
    int d  = idx % D_;
    int rb = idx / D_;
    int b  = rb % B_;
    int j  = 63 + rb / B_;
    size_t zr = ((size_t)j * B_ + b) * FD;
    float i_ = sigm(g_Z[zr + d]);
    float o_ = sigm(g_Z[zr + D_ + d]);
    float u_ = tanhf(g_Z[zr + 2 * D_ + d]);
    float c  = i_ * u_;
    g_C[((size_t)j * B_ + b) * D_ + d] = c;
    out[((size_t)b * N_ + j) * D_ + d] = o_ * tanhf(c);
}

// ---- internal level combine ----
__global__ void comb_k(int start, int n, float* __restrict__ out) {
    int idx = blockIdx.x * blockDim.x + threadIdx.x;
    int total = n * B_ * D_;
    if (idx >= total) return;
    int d  = idx % D_;
    int rb = idx / D_;
    int b  = rb % B_;
    int j  = start + rb / B_;
    int a  = 2 * j + 1;
    int a2 = 2 * j + 2;
    size_t zr = ((size_t)j  * B_ + b) * FD;
    size_t pa = ((size_t)a  * B_ + b) * FD;
    size_t pb = ((size_t)a2 * B_ + b) * FD;

    float ii = sigm (g_Z[zr + d]          + g_P[pa + d]          + g_P[pb + d]);
    float oo = sigm (g_Z[zr + D_ + d]     + g_P[pa + D_ + d]     + g_P[pb + D_ + d]);
    float uu = tanhf(g_Z[zr + 2*D_ + d]   + g_P[pa + 2*D_ + d]   + g_P[pb + 2*D_ + d]);
    float zf = g_Z[zr + 3 * D_ + d];
    float fa = sigm(g_P[pa + 3 * D_ + d] + zf);
    float fb = sigm(g_P[pb + 3 * D_ + d] + zf);

    float ca = g_C[((size_t)a  * B_ + b) * D_ + d];
    float cb = g_C[((size_t)a2 * B_ + b) * D_ + d];
    float cc = ii * uu + fa * ca + fb * cb;
    g_C[((size_t)j * B_ + b) * D_ + d] = cc;
    out[((size_t)b * N_ + j) * D_ + d] = oo * tanhf(cc);
}

extern "C" void kernel_launch(void* const* d_in, const int* in_sizes, int n_in,
                              void* d_out, int out_size) {
    const float* x     = (const float*)d_in[0];
    const float* Wioux = (const float*)d_in[1];
    const float* bioux = (const float*)d_in[2];
    const float* Wiouh = (const float*)d_in[3];
    const float* biouh = (const float*)d_in[4];
    const float* Wfx   = (const float*)d_in[5];
    const float* bfx   = (const float*)d_in[6];
    const float* Wfh   = (const float*)d_in[7];
    const float* bfh   = (const float*)d_in[8];
    float* out = (float*)d_out;

    float *Zp, *Pp, *Wcp, *W2p, *bcp;
    cudaGetSymbolAddress((void**)&Zp,  g_Z);
    cudaGetSymbolAddress((void**)&Pp,  g_P);
    cudaGetSymbolAddress((void**)&Wcp, g_Wc);
    cudaGetSymbolAddress((void**)&W2p, g_W2);
    cudaGetSymbolAddress((void**)&bcp, g_bc);

    // 1. pack weights / biases
    pack_k<<<(D_ * FD + 255) / 256, 256>>>(Wioux, bioux, Wiouh, biouh, Wfx, bfx, Wfh, bfh);

    // 2. Z = x @ [Wioux|Wfx] + bias, for ALL nodes  (M = 127*512 = 65024)
    {
        dim3 grid((N_ * B_) / BM, (FD + BN - 1) / BN);
        gemm_k<<<grid, 256>>>(x, 0, Wcp, bcp, Zp);
    }

    // 3. leaves
    leaf_k<<<(64 * B_ * D_ + 255) / 256, 256>>>(out);

    // 4. P for leaves  (M = 64*512 = 32768)
    {
        dim3 grid((64 * B_) / BM, (FD + BN - 1) / BN);
        gemm_k<<<grid, 256>>>(out, 63, W2p, nullptr, Pp + (size_t)63 * B_ * FD);
    }

    // 5. levels 5 .. 0
    for (int lev = 5; lev >= 0; --lev) {
        int s = (1 << lev) - 1;
        int n = 1 << lev;
        comb_k<<<(n * B_ * D_ + 255) / 256, 256>>>(s, n, out);
        if (lev > 0) {
            dim3 grid((n * B_) / BM, (FD + BN - 1) / BN);
            gemm_k<<<grid, 256>>>(out, s, W2p, nullptr, Pp + (size_t)s * B_ * FD);
        }
    }
    (void)in_sizes; (void)n_in; (void)out_size;
}

// round 4
// speedup vs baseline: 2.2419x; 2.2419x over previous
#include <cuda_runtime.h>
#include <cuda_bf16.h>
#include <cstdint>

#define B_  512
#define N_  127
#define D_  300
#define FD  1200    // 4*D : [i | o | u | f]
#define FDP 1280    // padded col stride for Z/P  (10 tiles of 128)
#define AK  320     // padded K stride (10 chunks of 32)
#define WK  320

// ---------------- scratch (static device allocations) ----------------
__device__ float g_Z[(size_t)N_ * B_ * FDP];         // x @ [Wioux|Wfx] + bias
__device__ float g_P[(size_t)N_ * B_ * FDP];         // h @ [Wiouh|Wfh]
__device__ float g_C[(size_t)N_ * B_ * D_];          // cell states
__device__ unsigned short g_x_hi[(size_t)N_ * B_ * AK];
__device__ unsigned short g_x_lo[(size_t)N_ * B_ * AK];
__device__ unsigned short g_h_hi[(size_t)N_ * B_ * AK];
__device__ unsigned short g_h_lo[(size_t)N_ * B_ * AK];
__device__ unsigned short g_WtC_hi[FDP * WK];        // [Wioux|Wfx]^T  (n-major, k-contig)
__device__ unsigned short g_WtC_lo[FDP * WK];
__device__ unsigned short g_Wt2_hi[FDP * WK];        // [Wiouh|Wfh]^T
__device__ unsigned short g_Wt2_lo[FDP * WK];
__device__ float g_bc[FDP];                          // combined bias for Z (pads zero)

__device__ __forceinline__ float sigm(float x) { return 1.0f / (1.0f + __expf(-x)); }

// ---------------- PTX helpers (sm_80-era; compile on plain sm_103) ----------------
__device__ __forceinline__ uint32_t smem_u32(const void* p) {
    uint32_t a;
    asm("{ .reg .u64 t; cvta.to.shared.u64 t, %1; cvt.u32.u64 %0, t; }" : "=r"(a) : "l"(p));
    return a;
}
__device__ __forceinline__ void cp16(uint32_t dst, const void* src) {
    uint64_t gsrc;
    asm("cvta.to.global.u64 %0, %1;" : "=l"(gsrc) : "l"(src));
    asm volatile("cp.async.cg.shared.global [%0], [%1], 16;" :: "r"(dst), "l"(gsrc));
}
#define CP_COMMIT() asm volatile("cp.async.commit_group;" ::: "memory")
#define CP_WAIT(n)  asm volatile("cp.async.wait_group %0;" :: "n"(n) : "memory")

__device__ __forceinline__ void ldsm4(uint32_t* r, uint32_t addr) {
    asm volatile("ldmatrix.sync.aligned.m8n8.x4.shared.b16 {%0,%1,%2,%3}, [%4];"
                 : "=r"(r[0]), "=r"(r[1]), "=r"(r[2]), "=r"(r[3]) : "r"(addr));
}
__device__ __forceinline__ void mma16816(float* c, const uint32_t* a, uint32_t b0, uint32_t b1) {
    asm volatile(
        "mma.sync.aligned.m16n8k16.row.col.f32.bf16.bf16.f32 "
        "{%0,%1,%2,%3}, {%4,%5,%6,%7}, {%8,%9}, {%0,%1,%2,%3};"
        : "+f"(c[0]), "+f"(c[1]), "+f"(c[2]), "+f"(c[3])
        : "r"(a[0]), "r"(a[1]), "r"(a[2]), "r"(a[3]), "r"(b0), "r"(b1));
}

// ---------------- pack weights: transpose + bf16 hi/lo split + combined bias ----------------
__global__ void pack_k(const float* __restrict__ Wioux, const float* __restrict__ bioux,
                       const float* __restrict__ Wiouh, const float* __restrict__ biouh,
                       const float* __restrict__ Wfx,  const float* __restrict__ bfx,
                       const float* __restrict__ Wfh,  const float* __restrict__ bfh) {
    int idx = blockIdx.x * blockDim.x + threadIdx.x;
    if (idx >= FDP * WK) return;
    int n = idx / WK, k = idx % WK;
    float wc = 0.0f, w2 = 0.0f;
    if (k < D_ && n < FD) {
        if (n < 3 * D_) { wc = Wioux[k * 3 * D_ + n]; w2 = Wiouh[k * 3 * D_ + n]; }
        else            { wc = Wfx[k * D_ + n - 3 * D_]; w2 = Wfh[k * D_ + n - 3 * D_]; }
    }
    __nv_bfloat16 wch = __float2bfloat16(wc);
    __nv_bfloat16 w2h = __float2bfloat16(w2);
    g_WtC_hi[idx] = __bfloat16_as_ushort(wch);
    g_WtC_lo[idx] = __bfloat16_as_ushort(__float2bfloat16(wc - __bfloat162float(wch)));
    g_Wt2_hi[idx] = __bfloat16_as_ushort(w2h);
    g_Wt2_lo[idx] = __bfloat16_as_ushort(__float2bfloat16(w2 - __bfloat162float(w2h)));
    if (idx < FDP)
        g_bc[idx] = (idx >= FD) ? 0.0f
                  : (idx < 3 * D_) ? (bioux[idx] + biouh[idx])
                                   : (bfx[idx - 3 * D_] + bfh[idx - 3 * D_]);
}

// ---------------- convert x (fp32) -> bf16 hi/lo, padded K stride ----------------
__global__ void xconv_k(const float* __restrict__ x) {
    int idx = blockIdx.x * blockDim.x + threadIdx.x;
    const int pairs = AK / 2;                       // 160
    if (idx >= N_ * B_ * pairs) return;
    int r  = idx / pairs;
    int k  = (idx % pairs) * 2;
    if (k >= D_) return;                            // pads stay zero (static init)
    float a0 = x[(size_t)r * D_ + k];
    float a1 = x[(size_t)r * D_ + k + 1];
    __nv_bfloat16 h0 = __float2bfloat16(a0);
    __nv_bfloat16 h1 = __float2bfloat16(a1);
    __nv_bfloat16 l0 = __float2bfloat16(a0 - __bfloat162float(h0));
    __nv_bfloat16 l1 = __float2bfloat16(a1 - __bfloat162float(h1));
    uint32_t hh = (uint32_t)__bfloat16_as_ushort(h0) | ((uint32_t)__bfloat16_as_ushort(h1) << 16);
    uint32_t ll = (uint32_t)__bfloat16_as_ushort(l0) | ((uint32_t)__bfloat16_as_ushort(l1) << 16);
    *(uint32_t*)(g_x_hi + (size_t)r * AK + k) = hh;
    *(uint32_t*)(g_x_lo + (size_t)r * AK + k) = ll;
}

// ---------------- mma.sync split-bf16 GEMM ----------------
// Block tile 128x128, K-tile 32, 2-stage cp.async pipeline, 8 warps (2m x 4n),
// warp tile 64x32, m16n8k16 bf16, 3-term split accumulation in fp32.
// A row R -> node j = node_start + R/512, batch b = R%512; row ptr (b*127+j)*AK.
// Out has col stride FDP (pads make every store in-bounds, no guards).
#define GT_THREADS 256
#define SROW 40                     // padded smem row (bf16 elems) = 80B, conflict-free
#define TILE_B (128 * SROW * 2)     // 10240 bytes per (buf) tile
#define STAGE_B (4 * TILE_B)        // Ahi,Alo,Bhi,Blo
#define SMEM_DYN (2 * STAGE_B)      // 81920

__global__ __launch_bounds__(GT_THREADS) void gemm_m(
    const unsigned short* __restrict__ Ahi, const unsigned short* __restrict__ Alo,
    int node_start,
    const unsigned short* __restrict__ Bhi, const unsigned short* __restrict__ Blo,
    const float* __restrict__ bias, float* __restrict__ Out)
{
    extern __shared__ char dsm[];
    const uint32_t sbase = smem_u32(dsm);

    const int t   = threadIdx.x;
    const int wid = t >> 5, lid = t & 31;
    const int row0 = blockIdx.x * 128;
    const int col0 = blockIdx.y * 128;
    const int wm = (wid >> 2) * 64;      // warp m offset (0/64)
    const int wn = (wid & 3) * 32;       // warp n offset (0/32/64/96)

    float acc[4][4][4];
#pragma unroll
    for (int i = 0; i < 4; i++)
#pragma unroll
        for (int j = 0; j < 4; j++)
#pragma unroll
            for (int k = 0; k < 4; k++) acc[i][j][k] = 0.0f;

    // ---- async loader for one stage ----
    auto load_stage = [&](int stage, int kt) {
        uint32_t sb = sbase + stage * STAGE_B;
        // A tiles: hi+lo, 512 16B-chunks each
#pragma unroll
        for (int i = 0; i < 4; ++i) {
            int idx = i * GT_THREADS + t;          // 0..1023
            int buf = idx >> 9;                    // 0=hi 1=lo
            int rem = idx & 511;
            int row = rem >> 2, part = rem & 3;
            int R = row0 + row;
            int j = node_start + (R >> 9);
            int b = R & (B_ - 1);
            const unsigned short* src =
                (buf ? Alo : Ahi) + ((size_t)b * N_ + j) * AK + kt + part * 8;
            cp16(sb + buf * TILE_B + row * (SROW * 2) + part * 16, src);
        }
        // B tiles: hi+lo
#pragma unroll
        for (int i = 0; i < 4; ++i) {
            int idx = i * GT_THREADS + t;
            int buf = idx >> 9;
            int rem = idx & 511;
            int row = rem >> 2, part = rem & 3;
            const unsigned short* src =
                (buf ? Blo : Bhi) + (size_t)(col0 + row) * WK + kt + part * 8;
            cp16(sb + 2 * TILE_B + buf * TILE_B + row * (SROW * 2) + part * 16, src);
        }
    };

    // ---- compute one stage ----
    const int lr = lid & 15, lc = (lid >> 4) * 8;
    auto compute_stage = [&](int stage) {
        uint32_t sA = sbase + stage * STAGE_B;
        uint32_t sB = sA + 2 * TILE_B;
#pragma unroll
        for (int ks = 0; ks < 32; ks += 16) {
            uint32_t a_hi[4][4], a_lo[4][4];
#pragma unroll
            for (int mt = 0; mt < 4; ++mt) {
                uint32_t ad = sA + ((wm + mt * 16 + lr) * SROW + ks + lc) * 2;
                ldsm4(a_hi[mt], ad);
                ldsm4(a_lo[mt], ad + TILE_B);
            }
            uint32_t b_hi[2][4], b_lo[2][4];
#pragma unroll
            for (int nh = 0; nh < 2; ++nh) {
                uint32_t bd = sB + ((wn + nh * 16 + lr) * SROW + ks + lc) * 2;
                ldsm4(b_hi[nh], bd);
                ldsm4(b_lo[nh], bd + TILE_B);
            }
#pragma unroll
            for (int mt = 0; mt < 4; ++mt)
#pragma unroll
                for (int nt = 0; nt < 4; ++nt) {
                    uint32_t bh0 = b_hi[nt >> 1][nt & 1], bh1 = b_hi[nt >> 1][(nt & 1) + 2];
                    uint32_t bl0 = b_lo[nt >> 1][nt & 1], bl1 = b_lo[nt >> 1][(nt & 1) + 2];
                    mma16816(acc[mt][nt], a_hi[mt], bh0, bh1);
                    mma16816(acc[mt][nt], a_hi[mt], bl0, bl1);
                    mma16816(acc[mt][nt], a_lo[mt], bh0, bh1);
                }
        }
    };

    // ---- pipeline: 10 K-iterations ----
    load_stage(0, 0);
    CP_COMMIT();
#pragma unroll 1
    for (int it = 0; it < 10; ++it) {
        if (it + 1 < 10) {
            load_stage((it + 1) & 1, (it + 1) * 32);
            CP_COMMIT();
            CP_WAIT(1);
        } else {
            CP_WAIT(0);
        }
        __syncthreads();
        compute_stage(it & 1);
        __syncthreads();
    }

    // ---- epilogue ----
    const int g = lid >> 2, i4 = lid & 3;
#pragma unroll
    for (int mt = 0; mt < 4; ++mt) {
        int r0 = row0 + wm + mt * 16 + g;
#pragma unroll
        for (int nt = 0; nt < 4; ++nt) {
            int cc = col0 + wn + nt * 8 + i4 * 2;
            float b0v = 0.0f, b1v = 0.0f;
            if (bias) { b0v = bias[cc]; b1v = bias[cc + 1]; }
            float* o0 = Out + (size_t)r0 * FDP + cc;
            float* o1 = Out + (size_t)(r0 + 8) * FDP + cc;
            o0[0] = acc[mt][nt][0] + b0v;
            o0[1] = acc[mt][nt][1] + b1v;
            o1[0] = acc[mt][nt][2] + b0v;
            o1[1] = acc[mt][nt][3] + b1v;
        }
    }
}

// ---------------- leaves: c = sig(z_i)*tanh(z_u); h = sig(z_o)*tanh(c) ----------------
__global__ void leaf_k(float* __restrict__ out) {
    int idx = blockIdx.x * blockDim.x + threadIdx.x;
    const int total = 64 * B_ * D_;
    if (idx >= total) return;
    int d  = idx % D_;
    int rb = idx / D_;
    int b  = rb % B_;
    int j  = 63 + rb / B_;
    size_t zr = ((size_t)j * B_ + b) * FDP;
    float i_ = sigm(g_Z[zr + d]);
    float o_ = sigm(g_Z[zr + D_ + d]);
    float u_ = tanhf(g_Z[zr + 2 * D_ + d]);
    float c  = i_ * u_;
    g_C[((size_t)j * B_ + b) * D_ + d] = c;
    float hh = o_ * tanhf(c);
    size_t ro = (size_t)b * N_ + j;
    out[ro * D_ + d] = hh;
    __nv_bfloat16 hb = __float2bfloat16(hh);
    g_h_hi[ro * AK + d] = __bfloat16_as_ushort(hb);
    g_h_lo[ro * AK + d] = __bfloat16_as_ushort(__float2bfloat16(hh - __bfloat162float(hb)));
}

// ---------------- internal level combine ----------------
__global__ void comb_k(int start, int n, float* __restrict__ out) {
    int idx = blockIdx.x * blockDim.x + threadIdx.x;
    int total = n * B_ * D_;
    if (idx >= total) return;
    int d  = idx % D_;
    int rb = idx / D_;
    int b  = rb % B_;
    int j  = start + rb / B_;
    int a  = 2 * j + 1;
    int a2 = 2 * j + 2;
    size_t zr = ((size_t)j  * B_ + b) * FDP;
    size_t pa = ((size_t)a  * B_ + b) * FDP;
    size_t pb = ((size_t)a2 * B_ + b) * FDP;

    float ii = sigm (g_Z[zr + d]          + g_P[pa + d]          + g_P[pb + d]);
    float oo = sigm (g_Z[zr + D_ + d]     + g_P[pa + D_ + d]     + g_P[pb + D_ + d]);
    float uu = tanhf(g_Z[zr + 2*D_ + d]   + g_P[pa + 2*D_ + d]   + g_P[pb + 2*D_ + d]);
    float zf = g_Z[zr + 3 * D_ + d];
    float fa = sigm(g_P[pa + 3 * D_ + d] + zf);
    float fb = sigm(g_P[pb + 3 * D_ + d] + zf);

    float ca = g_C[((size_t)a  * B_ + b) * D_ + d];
    float cb = g_C[((size_t)a2 * B_ + b) * D_ + d];
    float cc = ii * uu + fa * ca + fb * cb;
    g_C[((size_t)j * B_ + b) * D_ + d] = cc;
    float hh = oo * tanhf(cc);
    size_t ro = (size_t)b * N_ + j;
    out[ro * D_ + d] = hh;
    __nv_bfloat16 hb = __float2bfloat16(hh);
    g_h_hi[ro * AK + d] = __bfloat16_as_ushort(hb);
    g_h_lo[ro * AK + d] = __bfloat16_as_ushort(__float2bfloat16(hh - __bfloat162float(hb)));
}

extern "C" void kernel_launch(void* const* d_in, const int* in_sizes, int n_in,
                              void* d_out, int out_size) {
    const float* x     = (const float*)d_in[0];
    const float* Wioux = (const float*)d_in[1];
    const float* bioux = (const float*)d_in[2];
    const float* Wiouh = (const float*)d_in[3];
    const float* biouh = (const float*)d_in[4];
    const float* Wfx   = (const float*)d_in[5];
    const float* bfx   = (const float*)d_in[6];
    const float* Wfh   = (const float*)d_in[7];
    const float* bfh   = (const float*)d_in[8];
    float* out = (float*)d_out;

    float *Zp, *Pp, *bcp;
    unsigned short *xh, *xl, *hh, *hl, *wch, *wcl, *w2h, *w2l;
    cudaGetSymbolAddress((void**)&Zp,  g_Z);
    cudaGetSymbolAddress((void**)&Pp,  g_P);
    cudaGetSymbolAddress((void**)&bcp, g_bc);
    cudaGetSymbolAddress((void**)&xh,  g_x_hi);
    cudaGetSymbolAddress((void**)&xl,  g_x_lo);
    cudaGetSymbolAddress((void**)&hh,  g_h_hi);
    cudaGetSymbolAddress((void**)&hl,  g_h_lo);
    cudaGetSymbolAddress((void**)&wch, g_WtC_hi);
    cudaGetSymbolAddress((void**)&wcl, g_WtC_lo);
    cudaGetSymbolAddress((void**)&w2h, g_Wt2_hi);
    cudaGetSymbolAddress((void**)&w2l, g_Wt2_lo);

    cudaFuncSetAttribute(gemm_m, cudaFuncAttributeMaxDynamicSharedMemorySize, SMEM_DYN);

    // 1. pack weights (transpose + split) + combined bias
    pack_k<<<(FDP * WK + 255) / 256, 256>>>(Wioux, bioux, Wiouh, biouh, Wfx, bfx, Wfh, bfh);

    // 2. split x into bf16 hi/lo
    xconv_k<<<(N_ * B_ * (AK / 2) + 255) / 256, 256>>>(x);

    // 3. Z = x @ [Wioux|Wfx] + bias, all nodes  (M = 65024)
    {
        dim3 grid((N_ * B_) / 128, FDP / 128);
        gemm_m<<<grid, GT_THREADS, SMEM_DYN>>>(xh, xl, 0, wch, wcl, bcp, Zp);
    }

    // 4. leaves
    leaf_k<<<(64 * B_ * D_ + 255) / 256, 256>>>(out);

    // 5. P for leaves (M = 32768)
    {
        dim3 grid((64 * B_) / 128, FDP / 128);
        gemm_m<<<grid, GT_THREADS, SMEM_DYN>>>(hh, hl, 63, w2h, w2l, nullptr,
                                               Pp + (size_t)63 * B_ * FDP);
    }

    // 6. levels 5 .. 0
    for (int lev = 5; lev >= 0; --lev) {
        int s = (1 << lev) - 1;
        int n = 1 << lev;
        comb_k<<<(n * B_ * D_ + 255) / 256, 256>>>(s, n, out);
        if (lev > 0) {
            dim3 grid((n * B_) / 128, FDP / 128);
            gemm_m<<<grid, GT_THREADS, SMEM_DYN>>>(hh, hl, s, w2h, w2l, nullptr,
                                                   Pp + (size_t)s * B_ * FDP);
        }
    }
    (void)in_sizes; (void)n_in; (void)out_size;
}